// round 1
// baseline (speedup 1.0000x reference)
#include <cuda_runtime.h>
#include <cuda_bf16.h>
#include <cstdint>

// Problem constants (fixed shapes from setup_inputs)
#define TT 16          // time steps
#define BB 16          // batch
#define CC 256         // channels C (and Cc)
#define DD 512         // 2*C
#define HW 1024        // H*W = 32*32
#define NF4 16777216   // total float4 elements = T*B*C*HW/4

// Scratch (no allocation allowed)
__device__ float g_spikes[TT * BB * CC];   // [T,B,Cc]
__device__ float g_params[TT * BB * DD];   // [T,B,2C]

// ---------------------------------------------------------------------------
// Stage 1: LIF multistep scan over condition [T,B,Cc]
// One thread per (b,cc) lane; sequential over T (inherent dependence).
// v = v + (x - v)*0.5 ; s = (v-1 >= 0) ; v = (1-s)*v   (hard reset to 0)
// ---------------------------------------------------------------------------
__global__ void lif_kernel(const float* __restrict__ cond) {
    int i = blockIdx.x * blockDim.x + threadIdx.x;   // b*Cc + cc
    if (i >= BB * CC) return;
    float v = 0.0f;
#pragma unroll
    for (int t = 0; t < TT; ++t) {
        float x = cond[t * (BB * CC) + i];
        v = v + (x - v) * 0.5f;                  // charge (TAU=2)
        float s = (v >= 1.0f) ? 1.0f : 0.0f;     // fire
        g_spikes[t * (BB * CC) + i] = s;
        v = (1.0f - s) * v;                      // hard reset (v_reset=0)
    }
}

// ---------------------------------------------------------------------------
// Stage 2: params[t,b,d] = sum_c spikes[t,b,c] * W[d,c] + bias[d]
// One block per batch b (16 blocks), 512 threads (one per d).
// Spikes tile for all T in smem (broadcast reads -> conflict free).
// 16 accumulators/thread so each W element is read exactly once per block.
// ---------------------------------------------------------------------------
__global__ void gemm_kernel(const float* __restrict__ Wm,
                            const float* __restrict__ bias) {
    __shared__ float s_sp[TT][CC];   // 16 KB
    int b = blockIdx.x;
    for (int i = threadIdx.x; i < TT * CC; i += blockDim.x) {
        int t = i >> 8;          // / CC
        int c = i & (CC - 1);
        s_sp[t][c] = g_spikes[(t * BB + b) * CC + c];
    }
    __syncthreads();

    int d = threadIdx.x;         // 0..511
    float bd = bias[d];
    float acc[TT];
#pragma unroll
    for (int t = 0; t < TT; ++t) acc[t] = bd;

    const float* __restrict__ wrow = Wm + (size_t)d * CC;
#pragma unroll 4
    for (int k = 0; k < CC; ++k) {
        float w = wrow[k];
#pragma unroll
        for (int t = 0; t < TT; ++t)
            acc[t] = fmaf(s_sp[t][k], w, acc[t]);
    }
#pragma unroll
    for (int t = 0; t < TT; ++t)
        g_params[(t * BB + b) * DD + d] = acc[t];
}

// ---------------------------------------------------------------------------
// Stage 3: FiLM elementwise over 67M floats (HBM-bound).
// Block = 256 threads, each thread one float4 => block covers exactly one
// (t,b,c) channel (HW=1024 floats = 256 float4). gamma/beta are uniform
// per block (broadcast loads).  out = (1+gamma)*x + beta
// ---------------------------------------------------------------------------
__global__ void __launch_bounds__(256) film_kernel(
    const float4* __restrict__ x, float4* __restrict__ out) {
    unsigned row = blockIdx.x;           // (t*B + b)*C + c
    unsigned tb  = row >> 8;             // / C
    unsigned c   = row & (CC - 1);
    float g  = 1.0f + g_params[tb * DD + c];
    float be = g_params[tb * DD + CC + c];

    size_t i = (size_t)row * 256 + threadIdx.x;
    float4 v = x[i];
    float4 o;
    o.x = fmaf(g, v.x, be);
    o.y = fmaf(g, v.y, be);
    o.z = fmaf(g, v.z, be);
    o.w = fmaf(g, v.w, be);
    out[i] = o;
}

// ---------------------------------------------------------------------------
extern "C" void kernel_launch(void* const* d_in, const int* in_sizes, int n_in,
                              void* d_out, int out_size) {
    const float* x    = (const float*)d_in[0];   // [T,B,C,H,W]
    const float* cond = (const float*)d_in[1];   // [T,B,Cc]
    const float* Wm   = (const float*)d_in[2];   // [2C,Cc]
    const float* bias = (const float*)d_in[3];   // [2C]
    float* out = (float*)d_out;

    lif_kernel<<<(BB * CC + 255) / 256, 256>>>(cond);
    gemm_kernel<<<BB, DD>>>(Wm, bias);
    film_kernel<<<TT * BB * CC, 256>>>((const float4*)x, (float4*)out);
}

// round 2
// speedup vs baseline: 1.5355x; 1.5355x over previous
#include <cuda_runtime.h>
#include <cuda_bf16.h>
#include <cstdint>

#define TT 16          // time steps
#define BB 16          // batch
#define CC 256         // channels C (and Cc)
#define DD 512         // 2*C
#define HW 1024        // H*W

// Scratch (no allocation allowed)
__device__ float g_spikes[TT * BB * CC];   // [T,B,Cc]
__device__ float g_params[TT * BB * DD];   // [T,B,2C]

// ---------------------------------------------------------------------------
// Stage 1: LIF scan over condition [T,B,Cc]. One thread per (b,cc) lane.
// ---------------------------------------------------------------------------
__global__ void lif_kernel(const float* __restrict__ cond) {
    int i = blockIdx.x * blockDim.x + threadIdx.x;
    if (i >= BB * CC) return;
    float v = 0.0f;
#pragma unroll
    for (int t = 0; t < TT; ++t) {
        float x = cond[t * (BB * CC) + i];
        v = v + (x - v) * 0.5f;                  // charge (TAU=2)
        float s = (v >= 1.0f) ? 1.0f : 0.0f;     // fire
        g_spikes[t * (BB * CC) + i] = s;
        v = (1.0f - s) * v;                      // hard reset
    }
}

// ---------------------------------------------------------------------------
// Stage 2: params[t,b,d] = sum_c spikes[t,b,c]*W[d,c] + bias[d]
// Grid (16 batches x 4 d-chunks), 128 threads = one d each, acc over 16 t.
// W slice per block = 128 rows x 1KB = 128KB; spikes tile in smem.
// ---------------------------------------------------------------------------
__global__ void __launch_bounds__(128) gemm_kernel(
    const float* __restrict__ Wm, const float* __restrict__ bias) {
    __shared__ float s_sp[TT][CC];   // 16 KB
    int b = blockIdx.x;
    int d = blockIdx.y * 128 + threadIdx.x;

    for (int i = threadIdx.x; i < TT * CC; i += 128) {
        int t = i >> 8;
        int c = i & (CC - 1);
        s_sp[t][c] = g_spikes[(t * BB + b) * CC + c];
    }
    __syncthreads();

    float bd = bias[d];
    float acc[TT];
#pragma unroll
    for (int t = 0; t < TT; ++t) acc[t] = bd;

    const float* __restrict__ wrow = Wm + (size_t)d * CC;
#pragma unroll 4
    for (int k = 0; k < CC; ++k) {
        float w = wrow[k];
#pragma unroll
        for (int t = 0; t < TT; ++t)
            acc[t] = fmaf(s_sp[t][k], w, acc[t]);
    }
#pragma unroll
    for (int t = 0; t < TT; ++t)
        g_params[(t * BB + b) * DD + d] = acc[t];
}

// ---------------------------------------------------------------------------
// Stage 3: FiLM elementwise, HBM-bound. Each 256-thread block covers FOUR
// consecutive channels (4 x 1024 floats). All four float4 loads issued
// before any compute -> MLP=4 per thread. gamma/beta uniform per channel
// (broadcast scalar loads from L2-resident g_params).
// out = (1+gamma)*x + beta
// ---------------------------------------------------------------------------
__global__ void __launch_bounds__(256) film_kernel(
    const float4* __restrict__ x, float4* __restrict__ out) {
    unsigned row0 = blockIdx.x * 4;          // first channel-row of this block
    unsigned tb   = row0 >> 8;               // same for all 4 rows (aligned)
    unsigned c0   = row0 & (CC - 1);

    size_t base = (size_t)row0 * 256 + threadIdx.x;

    float4 v0 = x[base];
    float4 v1 = x[base + 256];
    float4 v2 = x[base + 512];
    float4 v3 = x[base + 768];

    const float* __restrict__ p = g_params + tb * DD + c0;
    float g0 = 1.0f + p[0],  b0 = p[CC + 0];
    float g1 = 1.0f + p[1],  b1 = p[CC + 1];
    float g2 = 1.0f + p[2],  b2 = p[CC + 2];
    float g3 = 1.0f + p[3],  b3 = p[CC + 3];

    float4 o;
    o.x = fmaf(g0, v0.x, b0); o.y = fmaf(g0, v0.y, b0);
    o.z = fmaf(g0, v0.z, b0); o.w = fmaf(g0, v0.w, b0);
    out[base] = o;
    o.x = fmaf(g1, v1.x, b1); o.y = fmaf(g1, v1.y, b1);
    o.z = fmaf(g1, v1.z, b1); o.w = fmaf(g1, v1.w, b1);
    out[base + 256] = o;
    o.x = fmaf(g2, v2.x, b2); o.y = fmaf(g2, v2.y, b2);
    o.z = fmaf(g2, v2.z, b2); o.w = fmaf(g2, v2.w, b2);
    out[base + 512] = o;
    o.x = fmaf(g3, v3.x, b3); o.y = fmaf(g3, v3.y, b3);
    o.z = fmaf(g3, v3.z, b3); o.w = fmaf(g3, v3.w, b3);
    out[base + 768] = o;
}

// ---------------------------------------------------------------------------
extern "C" void kernel_launch(void* const* d_in, const int* in_sizes, int n_in,
                              void* d_out, int out_size) {
    const float* x    = (const float*)d_in[0];   // [T,B,C,H,W]
    const float* cond = (const float*)d_in[1];   // [T,B,Cc]
    const float* Wm   = (const float*)d_in[2];   // [2C,Cc]
    const float* bias = (const float*)d_in[3];   // [2C]
    float* out = (float*)d_out;

    lif_kernel<<<(BB * CC + 255) / 256, 256>>>(cond);
    gemm_kernel<<<dim3(BB, 4), 128>>>(Wm, bias);
    film_kernel<<<TT * BB * CC / 4, 256>>>((const float4*)x, (float4*)out);
}